// round 4
// baseline (speedup 1.0000x reference)
#include <cuda_runtime.h>

// DeformationNetwork: fused MLP over 262144 points.
// Layers: in(60,pad64) -> 256 -> 256 -> [concat in] 316(pad320) -> 256 -> heads(3,4,3,1)
// fp32 compute using packed fma.rn.f32x2 (sm_103a FFMA2) for 2x fp32 FMA throughput.

#define NPTS      262144
#define TILE_M    64
#define NTHREADS  256
#define KC        32
#define WPAD      258          // 256 + 2: even (8B-aligned pair rows), conflict-free pair loads

typedef unsigned long long u64;

__device__ __forceinline__ u64 pack2(float lo, float hi) {
    u64 r; asm("mov.b64 %0, {%1,%2};" : "=l"(r) : "f"(lo), "f"(hi)); return r;
}
__device__ __forceinline__ void unpack2(u64 v, float& lo, float& hi) {
    asm("mov.b64 {%0,%1}, %2;" : "=f"(lo), "=f"(hi) : "l"(v));
}
__device__ __forceinline__ void ffma2(u64& d, u64 a, u64 b) {
    asm("fma.rn.f32x2 %0, %1, %2, %0;" : "+l"(d) : "l"(a), "l"(b));
}

// One hidden layer: outH[m][n] = relu(bias[n] + sum_k A[m][k] * W[n][k])
// A is read from segA for k < lenA, else segB at (k - lenA). W is [256][Kdim] row-major
// in global memory; zero-padded on the fly for k >= Kdim.
__device__ __forceinline__ void layer_gemm(
    const float* __restrict__ W, const float* __restrict__ bias,
    int Kdim, int nchunks,
    const float* segA, int strideA, int lenA,
    const float* segB, int strideB,
    float* sh_w, float* outH, int tid)
{
    const int lane = tid & 31;
    const int wid  = tid >> 5;     // 8 warps -> 8 m-blocks of 8 rows
    const int m0   = wid * 8;
    const int nb2  = lane * 2;     // this thread owns n in {nb2, nb2+1} + 64*j

    u64 acc[8][4];
    #pragma unroll
    for (int j = 0; j < 4; ++j) {
        u64 bj = *(const u64*)(bias + nb2 + 64 * j);
        #pragma unroll
        for (int i = 0; i < 8; ++i) acc[i][j] = bj;
    }

    for (int kc = 0; kc < nchunks; ++kc) {
        const int k0 = kc * KC;
        __syncthreads();   // previous chunk's sh_w reads (or pre-layer smem writes) done

        // Stage KC x 256 weights into sh_w[k*WPAD + n]; float4-coalesced global reads.
        #pragma unroll
        for (int it = 0; it < (KC * 256 / 4) / NTHREADS; ++it) {  // 8 iterations
            int f4 = tid + it * NTHREADS;      // 0..2047
            int n  = f4 >> 3;
            int k  = (f4 & 7) * 4;
            float4 v = make_float4(0.f, 0.f, 0.f, 0.f);
            if (k0 + k < Kdim)                 // Kdim is always a multiple of 4
                v = *(const float4*)(W + (size_t)n * Kdim + k0 + k);
            sh_w[(k + 0) * WPAD + n] = v.x;
            sh_w[(k + 1) * WPAD + n] = v.y;
            sh_w[(k + 2) * WPAD + n] = v.z;
            sh_w[(k + 3) * WPAD + n] = v.w;
        }
        __syncthreads();

        const float* ab; int as;
        if (k0 < lenA) { ab = segA + (size_t)m0 * strideA + k0;          as = strideA; }
        else           { ab = segB + (size_t)m0 * strideB + (k0 - lenA); as = strideB; }

        #pragma unroll 4
        for (int kk = 0; kk < KC; ++kk) {
            u64 bp[4];
            #pragma unroll
            for (int j = 0; j < 4; ++j)
                bp[j] = *(const u64*)(sh_w + kk * WPAD + nb2 + 64 * j);
            #pragma unroll
            for (int i = 0; i < 8; ++i) {
                float av = ab[i * as + kk];    // warp-broadcast LDS
                u64 ap = pack2(av, av);
                #pragma unroll
                for (int j = 0; j < 4; ++j) ffma2(acc[i][j], ap, bp[j]);
            }
        }
    }

    __syncthreads();   // all reads of input activations complete before overwrite
    #pragma unroll
    for (int i = 0; i < 8; ++i) {
        #pragma unroll
        for (int j = 0; j < 4; ++j) {
            float lo, hi; unpack2(acc[i][j], lo, hi);
            lo = fmaxf(lo, 0.f); hi = fmaxf(hi, 0.f);
            *(u64*)(outH + (size_t)(m0 + i) * 256 + nb2 + 64 * j) = pack2(lo, hi);
        }
    }
}

__global__ void __launch_bounds__(NTHREADS)
deform_kernel(
    const float* __restrict__ xyz,  const float* __restrict__ tptr,
    const float* __restrict__ W0,   const float* __restrict__ b0,
    const float* __restrict__ W1,   const float* __restrict__ b1,
    const float* __restrict__ W2,   const float* __restrict__ b2,
    const float* __restrict__ W3,   const float* __restrict__ b3,
    const float* __restrict__ Wxyz, const float* __restrict__ bxyz,
    const float* __restrict__ Wrot, const float* __restrict__ brot,
    const float* __restrict__ Wscale, const float* __restrict__ bscale,
    const float* __restrict__ Wop,  const float* __restrict__ bop,
    float* __restrict__ out)
{
    extern __shared__ float smem[];
    float* sh_x = smem;                       // 64 x 64   (input enc, cols 60..63 = 0)
    float* sh_h = smem + TILE_M * 64;         // 64 x 256  (activations)
    float* sh_w = sh_h + TILE_M * 256;        // KC x WPAD (weight staging)

    const int tid   = threadIdx.x;
    const int gbase = blockIdx.x * TILE_M;

    // ---- positional/time encoding into sh_x ----
    if (tid < TILE_M) {
        const int g = gbase + tid;
        float* row = sh_x + tid * 64;
        const float PI = 3.14159265358979323846f;
        float c0 = xyz[g * 3 + 0], c1 = xyz[g * 3 + 1], c2 = xyz[g * 3 + 2];
        row[0] = c0; row[1] = c1; row[2] = c2;
        float cv[3] = {c0, c1, c2};
        #pragma unroll
        for (int d = 0; d < 3; ++d) {
            float f = PI;
            #pragma unroll
            for (int i = 0; i < 6; ++i) {
                float s, cc; sincosf(cv[d] * f, &s, &cc);
                row[3 + d * 12 + i]     = s;
                row[3 + d * 12 + 6 + i] = cc;
                f *= 2.f;
            }
        }
        float t = tptr[0];
        row[39] = t;
        float f = PI;
        #pragma unroll
        for (int i = 0; i < 10; ++i) {
            float s, cc; sincosf(t * f, &s, &cc);
            row[40 + i] = s;
            row[50 + i] = cc;
            f *= 2.f;
        }
        row[60] = 0.f; row[61] = 0.f; row[62] = 0.f; row[63] = 0.f;
    }
    // layer_gemm's first __syncthreads() orders sh_x writes before reads.

    layer_gemm(W0, b0,  60,  2, sh_x,  64,  64, sh_x,  64, sh_w, sh_h, tid);
    layer_gemm(W1, b1, 256,  8, sh_h, 256, 256, sh_x,  64, sh_w, sh_h, tid);
    layer_gemm(W2, b2, 316, 10, sh_h, 256, 256, sh_x,  64, sh_w, sh_h, tid);  // skip concat
    layer_gemm(W3, b3, 256,  8, sh_h, 256, 256, sh_x,  64, sh_w, sh_h, tid);

    __syncthreads();

    // ---- output heads: 11 dot products of length 256 per point ----
    for (int idx = tid; idx < TILE_M * 16; idx += NTHREADS) {
        int m = idx >> 4, j = idx & 15;
        if (j >= 11) continue;
        const int g = gbase + m;
        const float* hw; float bv; float* dst;
        if (j < 3)       { hw = Wxyz   + j * 256;       bv = bxyz[j];       dst = out + (size_t)g * 3 + j; }
        else if (j < 7)  { hw = Wrot   + (j - 3) * 256; bv = brot[j - 3];   dst = out + (size_t)3 * NPTS + (size_t)g * 4 + (j - 3); }
        else if (j < 10) { hw = Wscale + (j - 7) * 256; bv = bscale[j - 7]; dst = out + (size_t)7 * NPTS + (size_t)g * 3 + (j - 7); }
        else             { hw = Wop;                    bv = bop[0];        dst = out + (size_t)10 * NPTS + g; }
        float s = bv;
        const float4* hv = (const float4*)(sh_h + m * 256);
        const float4* wv = (const float4*)hw;
        #pragma unroll 8
        for (int k = 0; k < 64; ++k) {
            float4 a = hv[k], b = wv[k];
            s += a.x * b.x + a.y * b.y + a.z * b.z + a.w * b.w;
        }
        *dst = s;
    }
}

extern "C" void kernel_launch(void* const* d_in, const int* in_sizes, int n_in,
                              void* d_out, int out_size) {
    const float* xyz    = (const float*)d_in[0];
    const float* tptr   = (const float*)d_in[1];
    const float* W0     = (const float*)d_in[2];
    const float* b0     = (const float*)d_in[3];
    const float* W1     = (const float*)d_in[4];
    const float* b1     = (const float*)d_in[5];
    const float* W2     = (const float*)d_in[6];
    const float* b2     = (const float*)d_in[7];
    const float* W3     = (const float*)d_in[8];
    const float* b3     = (const float*)d_in[9];
    const float* Wxyz   = (const float*)d_in[10];
    const float* bxyz   = (const float*)d_in[11];
    const float* Wrot   = (const float*)d_in[12];
    const float* brot   = (const float*)d_in[13];
    const float* Wscale = (const float*)d_in[14];
    const float* bscale = (const float*)d_in[15];
    const float* Wop    = (const float*)d_in[16];
    const float* bop    = (const float*)d_in[17];
    float* out = (float*)d_out;

    const size_t smem = (TILE_M * 64 + TILE_M * 256 + KC * WPAD) * sizeof(float);  // 114944 B
    cudaFuncSetAttribute(deform_kernel, cudaFuncAttributeMaxDynamicSharedMemorySize, (int)smem);
    deform_kernel<<<NPTS / TILE_M, NTHREADS, smem>>>(
        xyz, tptr, W0, b0, W1, b1, W2, b2, W3, b3,
        Wxyz, bxyz, Wrot, brot, Wscale, bscale, Wop, bop, out);
}